// round 1
// baseline (speedup 1.0000x reference)
#include <cuda_runtime.h>
#include <cuda_bf16.h>
#include <mma.h>
#include <math.h>

using namespace nvcuda;

// Normalized embeddings scratch (bf16): 8192 * 256 * 2B = 4 MB, L2-resident.
__device__ __nv_bfloat16 g_en[8192 * 256];

// ---------------------------------------------------------------------------
// Kernel 0: zero the (poisoned) output scalar.
// ---------------------------------------------------------------------------
__global__ void zero_out_kernel(float* out) { out[0] = 0.0f; }

// ---------------------------------------------------------------------------
// Kernel 1: row-normalize embeddings (fp32 -> bf16). One warp per row, D=256.
// blockDim = 256 (8 warps -> 8 rows per block).
// ---------------------------------------------------------------------------
__global__ void normalize_kernel(const float* __restrict__ emb, int B) {
    const int warpId = threadIdx.x >> 5;
    const int lane   = threadIdx.x & 31;
    const int row    = blockIdx.x * 8 + warpId;
    if (row >= B) return;

    const float4* p = reinterpret_cast<const float4*>(emb + (size_t)row * 256);
    float4 v0 = p[lane];        // elems [lane*4, lane*4+4)
    float4 v1 = p[lane + 32];   // elems [128 + lane*4, ...)

    float ss = v0.x * v0.x + v0.y * v0.y + v0.z * v0.z + v0.w * v0.w
             + v1.x * v1.x + v1.y * v1.y + v1.z * v1.z + v1.w * v1.w;
    #pragma unroll
    for (int o = 16; o > 0; o >>= 1) ss += __shfl_xor_sync(0xffffffffu, ss, o);

    const float scale = 1.0f / fmaxf(sqrtf(ss), 1e-8f);

    __nv_bfloat162 a0 = __floats2bfloat162_rn(v0.x * scale, v0.y * scale);
    __nv_bfloat162 a1 = __floats2bfloat162_rn(v0.z * scale, v0.w * scale);
    __nv_bfloat162 b0 = __floats2bfloat162_rn(v1.x * scale, v1.y * scale);
    __nv_bfloat162 b1 = __floats2bfloat162_rn(v1.z * scale, v1.w * scale);

    uint2 ua, ub;
    ua.x = *reinterpret_cast<unsigned*>(&a0);
    ua.y = *reinterpret_cast<unsigned*>(&a1);
    ub.x = *reinterpret_cast<unsigned*>(&b0);
    ub.y = *reinterpret_cast<unsigned*>(&b1);

    uint2* orow = reinterpret_cast<uint2*>(g_en + (size_t)row * 256);
    orow[lane]      = ua;   // 4 bf16 at elem lane*4
    orow[lane + 32] = ub;   // 4 bf16 at elem 128 + lane*4
}

// ---------------------------------------------------------------------------
// Kernel 2: fused cos-similarity GEMM tile + |text_sim - cos| masked reduction.
// 128x128 output tile per block, K = 256 fully staged in shared memory.
// Grid: (B/128, B/128); only blocks with bx >= by (upper-triangular) work.
// 8 warps, layout 4 (rows) x 2 (cols): each warp owns 32x64 via 2x4 WMMA frags.
// Dynamic smem: 128 KB (A strip 64 KB + B strip 64 KB), reused as fp32 cos tile.
// ---------------------------------------------------------------------------
__global__ __launch_bounds__(256, 1)
void loss_kernel(const float* __restrict__ text, float* __restrict__ out,
                 int B, float scale) {
    const int bx = blockIdx.x;
    const int by = blockIdx.y;
    if (bx < by) return;   // lower-triangular block: nothing to do

    extern __shared__ char smem[];
    __nv_bfloat16* As = reinterpret_cast<__nv_bfloat16*>(smem);   // [128][256]
    __nv_bfloat16* Bs = As + 128 * 256;                           // [128][256]

    const int tid = threadIdx.x;

    // --- stage A and B strips (each 128 rows x 256 bf16 = 64 KB) ---
    {
        const uint4* Ag = reinterpret_cast<const uint4*>(g_en + (size_t)by * 128 * 256);
        const uint4* Bg = reinterpret_cast<const uint4*>(g_en + (size_t)bx * 128 * 256);
        uint4* As4 = reinterpret_cast<uint4*>(As);
        uint4* Bs4 = reinterpret_cast<uint4*>(Bs);
        #pragma unroll
        for (int i = tid; i < 4096; i += 256) {   // 4096 uint4 per strip
            As4[i] = Ag[i];
            Bs4[i] = Bg[i];
        }
    }
    __syncthreads();

    // --- WMMA mainloop ---
    const int warpId = tid >> 5;
    const int wr = warpId & 3;   // 0..3 -> 32-row strips
    const int wc = warpId >> 2;  // 0..1 -> 64-col strips

    wmma::fragment<wmma::accumulator, 16, 16, 16, float> c[2][4];
    #pragma unroll
    for (int s = 0; s < 2; s++)
        #pragma unroll
        for (int t = 0; t < 4; t++)
            wmma::fill_fragment(c[s][t], 0.0f);

    #pragma unroll
    for (int k = 0; k < 256; k += 16) {
        wmma::fragment<wmma::matrix_a, 16, 16, 16, __nv_bfloat16, wmma::row_major> a[2];
        wmma::fragment<wmma::matrix_b, 16, 16, 16, __nv_bfloat16, wmma::col_major> b[4];
        #pragma unroll
        for (int s = 0; s < 2; s++)
            wmma::load_matrix_sync(a[s], As + (wr * 32 + s * 16) * 256 + k, 256);
        #pragma unroll
        for (int t = 0; t < 4; t++)
            wmma::load_matrix_sync(b[t], Bs + (wc * 64 + t * 16) * 256 + k, 256);
        #pragma unroll
        for (int s = 0; s < 2; s++)
            #pragma unroll
            for (int t = 0; t < 4; t++)
                wmma::mma_sync(c[s][t], a[s], b[t], c[s][t]);
    }
    __syncthreads();   // done reading As/Bs -> safe to overwrite smem

    // --- dump accumulators to smem as a 128x128 fp32 cos tile ---
    float* ct = reinterpret_cast<float*>(smem);   // [128][128], 64 KB
    #pragma unroll
    for (int s = 0; s < 2; s++)
        #pragma unroll
        for (int t = 0; t < 4; t++)
            wmma::store_matrix_sync(ct + (wr * 32 + s * 16) * 128 + wc * 64 + t * 16,
                                    c[s][t], 128, wmma::mem_row_major);
    __syncthreads();

    // --- epilogue: |text_sim - cos| with i<j mask, coalesced text_sim read ---
    const int r = tid >> 1;        // 0..127 row within tile
    const int h = tid & 1;         // half of the 128-col row
    const int gi = by * 128 + r;
    const int jbase = bx * 128 + h * 64;

    const float4* ts4 = reinterpret_cast<const float4*>(
        text + (size_t)gi * B + jbase);
    const float4* c4 = reinterpret_cast<const float4*>(ct + r * 128 + h * 64);

    float acc = 0.0f;
    #pragma unroll
    for (int q = 0; q < 16; q++) {
        float4 t4 = ts4[q];
        float4 v4 = c4[q];
        int j = jbase + q * 4;
        if (j + 0 > gi) acc += fabsf(t4.x - v4.x);
        if (j + 1 > gi) acc += fabsf(t4.y - v4.y);
        if (j + 2 > gi) acc += fabsf(t4.z - v4.z);
        if (j + 3 > gi) acc += fabsf(t4.w - v4.w);
    }

    __shared__ float red[256];
    red[tid] = acc;
    __syncthreads();
    #pragma unroll
    for (int s2 = 128; s2 > 0; s2 >>= 1) {
        if (tid < s2) red[tid] += red[tid + s2];
        __syncthreads();
    }
    if (tid == 0) atomicAdd(out, red[0] * scale);
}

// ---------------------------------------------------------------------------
// Launch
// ---------------------------------------------------------------------------
extern "C" void kernel_launch(void* const* d_in, const int* in_sizes, int n_in,
                              void* d_out, int out_size) {
    const float* emb  = (const float*)d_in[0];   // [B, D] fp32
    const float* text = (const float*)d_in[1];   // [B, B] fp32
    float* out = (float*)d_out;

    const int B = (int)(sqrt((double)in_sizes[1]) + 0.5);   // 8192
    // D = in_sizes[0] / B == 256 (kernels specialized for D=256)

    const double count = (double)B * (double)(B - 1) / 2.0;
    const float scale = (float)(0.1 / count);

    cudaFuncSetAttribute(loss_kernel,
                         cudaFuncAttributeMaxDynamicSharedMemorySize, 131072);

    zero_out_kernel<<<1, 1>>>(out);
    normalize_kernel<<<B / 8, 256>>>(emb, B);

    dim3 grid(B / 128, B / 128);
    loss_kernel<<<grid, 256, 131072>>>(text, out, B, scale);
}

// round 4
// speedup vs baseline: 2.2930x; 2.2930x over previous
#include <cuda_runtime.h>
#include <cuda_bf16.h>
#include <mma.h>
#include <cstdint>
#include <math.h>

using namespace nvcuda;

// Normalized embeddings scratch (bf16): 8192 * 256 * 2B = 4 MB, L2-resident.
__device__ __nv_bfloat16 g_en[8192 * 256];

// ---------------------------------------------------------------------------
// Kernel 0: zero the (poisoned) output scalar.
// ---------------------------------------------------------------------------
__global__ void zero_out_kernel(float* out) { out[0] = 0.0f; }

// ---------------------------------------------------------------------------
// Kernel 1: row-normalize embeddings (fp32 -> bf16). One warp per row, D=256.
// ---------------------------------------------------------------------------
__global__ void normalize_kernel(const float* __restrict__ emb, int B) {
    const int warpId = threadIdx.x >> 5;
    const int lane   = threadIdx.x & 31;
    const int row    = blockIdx.x * 8 + warpId;
    if (row >= B) return;

    const float4* p = reinterpret_cast<const float4*>(emb + (size_t)row * 256);
    float4 v0 = p[lane];
    float4 v1 = p[lane + 32];

    float ss = v0.x * v0.x + v0.y * v0.y + v0.z * v0.z + v0.w * v0.w
             + v1.x * v1.x + v1.y * v1.y + v1.z * v1.z + v1.w * v1.w;
    #pragma unroll
    for (int o = 16; o > 0; o >>= 1) ss += __shfl_xor_sync(0xffffffffu, ss, o);

    const float scale = 1.0f / fmaxf(sqrtf(ss), 1e-8f);

    __nv_bfloat162 a0 = __floats2bfloat162_rn(v0.x * scale, v0.y * scale);
    __nv_bfloat162 a1 = __floats2bfloat162_rn(v0.z * scale, v0.w * scale);
    __nv_bfloat162 b0 = __floats2bfloat162_rn(v1.x * scale, v1.y * scale);
    __nv_bfloat162 b1 = __floats2bfloat162_rn(v1.z * scale, v1.w * scale);

    uint2 ua, ub;
    ua.x = *reinterpret_cast<unsigned*>(&a0);
    ua.y = *reinterpret_cast<unsigned*>(&a1);
    ub.x = *reinterpret_cast<unsigned*>(&b0);
    ub.y = *reinterpret_cast<unsigned*>(&b1);

    uint2* orow = reinterpret_cast<uint2*>(g_en + (size_t)row * 256);
    orow[lane]      = ua;
    orow[lane + 32] = ub;
}

// ---------------------------------------------------------------------------
// Kernel 2: fused cos-GEMM tile + |text - cos| masked reduction (WMMA/HMMA).
//
// One CTA = one 128x128 upper-triangular tile, K = 256 fully staged.
// Anti-bank-conflict padding: operand strips stored with ldm = 264 bf16
// (528 B row stride; 528 mod 128 = 16 -> the 8 rows of each ldmatrix land in
// 8 distinct bank phases -> conflict-free fragment loads).
// text_sim tile (64 KB fp32) prefetched to smem via cp.async, overlapped with
// the WMMA mainloop. Epilogue: cos dumped to smem (ldm=132 fp32), fused
// masked |diff| + block reduction + one atomicAdd.
//
// smem layout (dynamic, 200704 B):
//   [0,          135168)  A strip 128x264 bf16 | B strip 128x264 bf16
//                          (reused after mainloop as cos tile 128x132 fp32)
//   [135168,     200704)  text tile 128x128 fp32
// ---------------------------------------------------------------------------
#define LDM_OP   264                       // bf16 elems per padded operand row
#define OP_BYTES (128 * LDM_OP * 2)        // 67584 per strip
#define SMEM_B_OFF  OP_BYTES               // B strip offset
#define SMEM_T_OFF  (2 * OP_BYTES)         // text tile offset (135168)
#define SMEM_TOTAL  (2 * OP_BYTES + 65536) // 200704
#define LDM_C    132                       // fp32 elems per padded cos row

__global__ __launch_bounds__(256, 1)
void loss_kernel(const float* __restrict__ text, float* __restrict__ out,
                 int B, float scale) {
    extern __shared__ char smem[];
    __nv_bfloat16* As = reinterpret_cast<__nv_bfloat16*>(smem);
    __nv_bfloat16* Bs = reinterpret_cast<__nv_bfloat16*>(smem + SMEM_B_OFF);
    float*         Ts = reinterpret_cast<float*>(smem + SMEM_T_OFF);

    const int tid = threadIdx.x;

    // ---- linear block id -> upper-triangular (by, bx), by <= bx ----
    const int NT = B >> 7;
    int t = blockIdx.x;
    int by = 0;
    while (t >= NT - by) { t -= NT - by; ++by; }
    const int bx = by + t;

    // ---- stage A and B strips into padded smem (row = 32 x 16B chunks) ----
    {
        const uint4* __restrict__ Ag =
            reinterpret_cast<const uint4*>(g_en + (size_t)by * 128 * 256);
        const uint4* __restrict__ Bg =
            reinterpret_cast<const uint4*>(g_en + (size_t)bx * 128 * 256);
        #pragma unroll
        for (int i = tid; i < 4096; i += 256) {
            const int r = i >> 5;          // row 0..127
            const int c = i & 31;          // 16B chunk within row
            const uint32_t off = (uint32_t)r * (LDM_OP * 2) + (uint32_t)c * 16;
            *reinterpret_cast<uint4*>(reinterpret_cast<char*>(As) + off) = Ag[i];
            *reinterpret_cast<uint4*>(reinterpret_cast<char*>(Bs) + off) = Bg[i];
        }
    }

    // ---- prefetch text tile via cp.async (overlaps with WMMA mainloop) ----
    {
        const char* __restrict__ tg = reinterpret_cast<const char*>(
            text + (size_t)(by * 128) * B + (size_t)bx * 128);
        uint32_t ts_base;
        asm("{ .reg .u64 t; cvta.to.shared.u64 t, %1; cvt.u32.u64 %0, t; }"
            : "=r"(ts_base) : "l"((const void*)Ts));
        #pragma unroll
        for (int i = tid; i < 4096; i += 256) {   // 4096 x 16B = 64 KB
            const int r = i >> 5;                 // tile row
            const int c = i & 31;                 // 16B chunk
            const uint32_t saddr = ts_base + (uint32_t)i * 16;
            const char* gaddr = tg + (size_t)r * B * 4 + (size_t)c * 16;
            asm volatile("cp.async.cg.shared.global [%0], [%1], 16;"
                         :: "r"(saddr), "l"(gaddr) : "memory");
        }
        asm volatile("cp.async.commit_group;" ::: "memory");
    }
    __syncthreads();

    // ---- WMMA mainloop: 8 warps, 4 (rows) x 2 (cols), each 32x64 ----
    const int warpId = tid >> 5;
    const int wr = warpId & 3;
    const int wc = warpId >> 2;

    wmma::fragment<wmma::accumulator, 16, 16, 16, float> c[2][4];
    #pragma unroll
    for (int s = 0; s < 2; s++)
        #pragma unroll
        for (int u = 0; u < 4; u++)
            wmma::fill_fragment(c[s][u], 0.0f);

    #pragma unroll
    for (int k = 0; k < 256; k += 16) {
        wmma::fragment<wmma::matrix_a, 16, 16, 16, __nv_bfloat16, wmma::row_major> a[2];
        wmma::fragment<wmma::matrix_b, 16, 16, 16, __nv_bfloat16, wmma::col_major> b[4];
        #pragma unroll
        for (int s = 0; s < 2; s++)
            wmma::load_matrix_sync(a[s], As + (wr * 32 + s * 16) * LDM_OP + k, LDM_OP);
        #pragma unroll
        for (int u = 0; u < 4; u++)
            wmma::load_matrix_sync(b[u], Bs + (wc * 64 + u * 16) * LDM_OP + k, LDM_OP);
        #pragma unroll
        for (int s = 0; s < 2; s++)
            #pragma unroll
            for (int u = 0; u < 4; u++)
                wmma::mma_sync(c[s][u], a[s], b[u], c[s][u]);
    }
    __syncthreads();   // all warps done reading As/Bs

    // ---- dump accumulators: 128x128 fp32 cos tile, padded ldm=132 ----
    float* ct = reinterpret_cast<float*>(smem);
    #pragma unroll
    for (int s = 0; s < 2; s++)
        #pragma unroll
        for (int u = 0; u < 4; u++)
            wmma::store_matrix_sync(ct + (wr * 32 + s * 16) * LDM_C + wc * 64 + u * 16,
                                    c[s][u], LDM_C, wmma::mem_row_major);
    asm volatile("cp.async.wait_group 0;" ::: "memory");
    __syncthreads();

    // ---- epilogue: |text - cos| with i<j mask, all from smem ----
    const int r = tid >> 1;        // tile row 0..127
    const int h = tid & 1;         // which 64-col half
    const int gi = by * 128 + r;
    const bool diag = (bx == by);

    const float4* c4 = reinterpret_cast<const float4*>(ct + r * LDM_C + h * 64);
    const float4* t4p = reinterpret_cast<const float4*>(Ts + r * 128 + h * 64);

    float acc = 0.0f;
    if (!diag) {
        #pragma unroll
        for (int q = 0; q < 16; q++) {
            float4 tv = t4p[q];
            float4 cv = c4[q];
            acc += fabsf(tv.x - cv.x) + fabsf(tv.y - cv.y)
                 + fabsf(tv.z - cv.z) + fabsf(tv.w - cv.w);
        }
    } else {
        #pragma unroll
        for (int q = 0; q < 16; q++) {
            float4 tv = t4p[q];
            float4 cv = c4[q];
            const int j = bx * 128 + h * 64 + q * 4;
            if (j + 0 > gi) acc += fabsf(tv.x - cv.x);
            if (j + 1 > gi) acc += fabsf(tv.y - cv.y);
            if (j + 2 > gi) acc += fabsf(tv.z - cv.z);
            if (j + 3 > gi) acc += fabsf(tv.w - cv.w);
        }
    }

    // ---- reduction: warp shuffle -> smem -> one atomicAdd ----
    #pragma unroll
    for (int o = 16; o > 0; o >>= 1) acc += __shfl_xor_sync(0xffffffffu, acc, o);

    __shared__ float red[8];
    if ((tid & 31) == 0) red[tid >> 5] = acc;
    __syncthreads();
    if (tid == 0) {
        float s = 0.0f;
        #pragma unroll
        for (int w = 0; w < 8; w++) s += red[w];
        atomicAdd(out, s * scale);
    }
}

// ---------------------------------------------------------------------------
// Launch
// ---------------------------------------------------------------------------
extern "C" void kernel_launch(void* const* d_in, const int* in_sizes, int n_in,
                              void* d_out, int out_size) {
    const float* emb  = (const float*)d_in[0];   // [B, D] fp32
    const float* text = (const float*)d_in[1];   // [B, B] fp32
    float* out = (float*)d_out;

    const int B = (int)(sqrt((double)in_sizes[1]) + 0.5);   // 8192
    const double count = (double)B * (double)(B - 1) / 2.0;
    const float scale = (float)(0.1 / count);

    cudaFuncSetAttribute(loss_kernel,
                         cudaFuncAttributeMaxDynamicSharedMemorySize, SMEM_TOTAL);

    zero_out_kernel<<<1, 1>>>(out);
    normalize_kernel<<<B / 8, 256>>>(emb, B);

    const int NT = B / 128;
    const int nblocks = NT * (NT + 1) / 2;   // 2080 upper-tri tiles
    loss_kernel<<<nblocks, 256, SMEM_TOTAL>>>(text, out, B, scale);
}

// round 5
// speedup vs baseline: 3.4614x; 1.5095x over previous
#include <cuda_runtime.h>
#include <cuda_bf16.h>
#include <cstdint>
#include <math.h>

// Normalized embeddings scratch (bf16): 8192 * 256 * 2B = 4 MB, L2-resident.
__device__ __nv_bfloat16 g_en[8192 * 256];

// ---------------------------------------------------------------------------
// Kernel 0: zero the (poisoned) output scalar.
// ---------------------------------------------------------------------------
__global__ void zero_out_kernel(float* out) { out[0] = 0.0f; }

// ---------------------------------------------------------------------------
// Kernel 1: row-normalize embeddings (fp32 -> bf16). One warp per row, D=256.
// ---------------------------------------------------------------------------
__global__ void normalize_kernel(const float* __restrict__ emb, int B) {
    const int warpId = threadIdx.x >> 5;
    const int lane   = threadIdx.x & 31;
    const int row    = blockIdx.x * 8 + warpId;
    if (row >= B) return;

    const float4* p = reinterpret_cast<const float4*>(emb + (size_t)row * 256);
    float4 v0 = p[lane];
    float4 v1 = p[lane + 32];

    float ss = v0.x * v0.x + v0.y * v0.y + v0.z * v0.z + v0.w * v0.w
             + v1.x * v1.x + v1.y * v1.y + v1.z * v1.z + v1.w * v1.w;
    #pragma unroll
    for (int o = 16; o > 0; o >>= 1) ss += __shfl_xor_sync(0xffffffffu, ss, o);

    const float scale = 1.0f / fmaxf(sqrtf(ss), 1e-8f);

    __nv_bfloat162 a0 = __floats2bfloat162_rn(v0.x * scale, v0.y * scale);
    __nv_bfloat162 a1 = __floats2bfloat162_rn(v0.z * scale, v0.w * scale);
    __nv_bfloat162 b0 = __floats2bfloat162_rn(v1.x * scale, v1.y * scale);
    __nv_bfloat162 b1 = __floats2bfloat162_rn(v1.z * scale, v1.w * scale);

    uint2 ua, ub;
    ua.x = *reinterpret_cast<unsigned*>(&a0);
    ua.y = *reinterpret_cast<unsigned*>(&a1);
    ub.x = *reinterpret_cast<unsigned*>(&b0);
    ub.y = *reinterpret_cast<unsigned*>(&b1);

    uint2* orow = reinterpret_cast<uint2*>(g_en + (size_t)row * 256);
    orow[lane]      = ua;
    orow[lane + 32] = ub;
}

// ---------------------------------------------------------------------------
// Kernel 2: fused cos-GEMM tile + |text - cos| masked reduction.
// Raw mma.sync.m16n8k16 (bf16 -> fp32) with in-register epilogue.
//
// One CTA = one 128x128 upper-triangular tile, K = 256.
// cp.async pipeline: group0 = A/B K[0:128), group1 = A/B K[128:256),
// group2 = text tile. MMA half 0 overlaps group1 + group2 transfers.
// Padding: operands ldm=264 bf16 (528 B rows), text ldm=132 fp32 (528 B rows)
// -> conflict-free ldmatrix and epilogue accesses.
//
// 8 warps, layout 4 (row) x 2 (col), each warp owns 32 x 64 of the tile:
// 2 m16 strips x 8 n8 strips of m16n8k16 accumulators.
// ---------------------------------------------------------------------------
#define LDM_OP   264                       // bf16 elems per padded operand row
#define OPB      (128 * LDM_OP * 2)        // 67584 bytes per operand strip
#define SMEM_A_OFF  0
#define SMEM_B_OFF  OPB
#define SMEM_T_OFF  (2 * OPB)              // 135168
#define LDM_T    132                       // fp32 elems per padded text row
#define SMEM_TOTAL  (2 * OPB + 128 * LDM_T * 4)   // 202752

#define LDSM4(R0, R1, R2, R3, ADDR)                                          \
    asm volatile("ldmatrix.sync.aligned.m8n8.x4.shared.b16 {%0,%1,%2,%3}, [%4];" \
                 : "=r"(R0), "=r"(R1), "=r"(R2), "=r"(R3) : "r"(ADDR))

#define MMA16816(C, A, B0, B1)                                               \
    asm volatile("mma.sync.aligned.m16n8k16.row.col.f32.bf16.bf16.f32 "      \
                 "{%0,%1,%2,%3}, {%4,%5,%6,%7}, {%8,%9}, {%0,%1,%2,%3};"     \
                 : "+f"((C)[0]), "+f"((C)[1]), "+f"((C)[2]), "+f"((C)[3])    \
                 : "r"((A)[0]), "r"((A)[1]), "r"((A)[2]), "r"((A)[3]),       \
                   "r"(B0), "r"(B1))

__global__ __launch_bounds__(256, 1)
void loss_kernel(const float* __restrict__ text, float* __restrict__ out,
                 int B, float scale) {
    extern __shared__ char smem[];
    uint32_t sbase;
    asm("{ .reg .u64 t; cvta.to.shared.u64 t, %1; cvt.u32.u64 %0, t; }"
        : "=r"(sbase) : "l"((const void*)smem));

    const int tid = threadIdx.x;

    // ---- linear block id -> upper-triangular (by, bx), by <= bx ----
    const int NT = B >> 7;
    int t = blockIdx.x;
    int by = 0;
    while (t >= NT - by) { t -= NT - by; ++by; }
    const int bx = by + t;

    // ---- cp.async staging: operands in two K-half groups, then text ----
    {
        const char* __restrict__ Ag =
            reinterpret_cast<const char*>(g_en + (size_t)by * 128 * 256);
        const char* __restrict__ Bg =
            reinterpret_cast<const char*>(g_en + (size_t)bx * 128 * 256);
        #pragma unroll
        for (int half = 0; half < 2; half++) {
            #pragma unroll
            for (int i = tid; i < 2048; i += 256) {        // 128 rows x 16 chunks
                const int r = i >> 4;
                const int c = (i & 15) + half * 16;        // 16B chunk in row
                const uint32_t soff = (uint32_t)r * 528 + (uint32_t)c * 16;
                const size_t   goff = (size_t)r * 512 + (size_t)c * 16;
                asm volatile("cp.async.cg.shared.global [%0], [%1], 16;"
                             :: "r"(sbase + SMEM_A_OFF + soff), "l"(Ag + goff)
                             : "memory");
                asm volatile("cp.async.cg.shared.global [%0], [%1], 16;"
                             :: "r"(sbase + SMEM_B_OFF + soff), "l"(Bg + goff)
                             : "memory");
            }
            asm volatile("cp.async.commit_group;" ::: "memory");
        }
        const char* __restrict__ tg = reinterpret_cast<const char*>(
            text + (size_t)(by * 128) * B + (size_t)bx * 128);
        #pragma unroll
        for (int i = tid; i < 4096; i += 256) {            // 128 rows x 32 chunks
            const int r = i >> 5;
            const int c = i & 31;
            asm volatile("cp.async.cg.shared.global [%0], [%1], 16;"
                         :: "r"(sbase + SMEM_T_OFF + (uint32_t)r * 528 + (uint32_t)c * 16),
                            "l"(tg + (size_t)r * B * 4 + (size_t)c * 16)
                         : "memory");
        }
        asm volatile("cp.async.commit_group;" ::: "memory");
    }

    // ---- warp / fragment geometry ----
    const int warpId = tid >> 5;
    const int lane   = tid & 31;
    const int wr = warpId & 3;    // 32-row strip
    const int wc = warpId >> 2;   // 64-col strip

    // ldmatrix per-lane base addresses (element offsets *2 bytes)
    // A (.x4): lanes 0-15 -> rows 0-15 @k, lanes 16-31 -> rows 0-15 @k+8
    const uint32_t aBase = sbase + SMEM_A_OFF +
        (uint32_t)(((wr * 32 + (lane & 15)) * LDM_OP + (lane >> 4) * 8) * 2);
    // B (.x4, two n8 tiles): grp0: n0-7@k, grp1: n0-7@k+8, grp2: n8-15@k, grp3: n8-15@k+8
    const int grp = lane >> 3;
    const uint32_t bBase = sbase + SMEM_B_OFF +
        (uint32_t)(((wc * 64 + (grp >> 1) * 8 + (lane & 7)) * LDM_OP + (grp & 1) * 8) * 2);

    float c[2][8][4];
    #pragma unroll
    for (int mt = 0; mt < 2; mt++)
        #pragma unroll
        for (int nt = 0; nt < 8; nt++)
            #pragma unroll
            for (int e = 0; e < 4; e++) c[mt][nt][e] = 0.0f;

    // ---- MMA mainloop, pipelined over two K-halves ----
    #pragma unroll
    for (int half = 0; half < 2; half++) {
        if (half == 0) {
            asm volatile("cp.async.wait_group 2;" ::: "memory");
        } else {
            asm volatile("cp.async.wait_group 1;" ::: "memory");
        }
        __syncthreads();

        #pragma unroll
        for (int kc = 0; kc < 8; kc++) {
            const uint32_t koff = (uint32_t)((half * 128 + kc * 16) * 2);
            uint32_t a[2][4];
            #pragma unroll
            for (int mt = 0; mt < 2; mt++)
                LDSM4(a[mt][0], a[mt][1], a[mt][2], a[mt][3],
                      aBase + (uint32_t)(mt * 16 * LDM_OP * 2) + koff);
            uint32_t b[4][4];   // [p][{b0_even, b1_even, b0_odd, b1_odd}]
            #pragma unroll
            for (int p = 0; p < 4; p++)
                LDSM4(b[p][0], b[p][1], b[p][2], b[p][3],
                      bBase + (uint32_t)(p * 16 * LDM_OP * 2) + koff);
            #pragma unroll
            for (int mt = 0; mt < 2; mt++)
                #pragma unroll
                for (int nt = 0; nt < 8; nt++)
                    MMA16816(c[mt][nt], a[mt],
                             b[nt >> 1][(nt & 1) * 2], b[nt >> 1][(nt & 1) * 2 + 1]);
        }
    }

    // ---- wait for text tile, then in-register epilogue ----
    asm volatile("cp.async.wait_group 0;" ::: "memory");
    __syncthreads();

    const float* __restrict__ Ts = reinterpret_cast<const float*>(smem + SMEM_T_OFF);
    const int qrow = lane >> 2;          // 0..7
    const int qcol = (lane & 3) * 2;     // 0,2,4,6
    const bool diag = (bx == by);

    float acc = 0.0f;
    #pragma unroll
    for (int mt = 0; mt < 2; mt++) {
        const int r0 = wr * 32 + mt * 16 + qrow;   // rows r0 and r0+8
        #pragma unroll
        for (int nt = 0; nt < 8; nt++) {
            const int cc = wc * 64 + nt * 8 + qcol;
            const float2 t0 = *reinterpret_cast<const float2*>(Ts + r0 * LDM_T + cc);
            const float2 t1 = *reinterpret_cast<const float2*>(Ts + (r0 + 8) * LDM_T + cc);
            const float* cf = c[mt][nt];
            if (!diag) {
                acc += fabsf(t0.x - cf[0]) + fabsf(t0.y - cf[1])
                     + fabsf(t1.x - cf[2]) + fabsf(t1.y - cf[3]);
            } else {
                if (cc     > r0)     acc += fabsf(t0.x - cf[0]);
                if (cc + 1 > r0)     acc += fabsf(t0.y - cf[1]);
                if (cc     > r0 + 8) acc += fabsf(t1.x - cf[2]);
                if (cc + 1 > r0 + 8) acc += fabsf(t1.y - cf[3]);
            }
        }
    }

    // ---- reduction: warp shuffle -> smem -> one atomicAdd ----
    #pragma unroll
    for (int o = 16; o > 0; o >>= 1) acc += __shfl_xor_sync(0xffffffffu, acc, o);

    __shared__ float red[8];
    if ((tid & 31) == 0) red[tid >> 5] = acc;
    __syncthreads();
    if (tid == 0) {
        float s = 0.0f;
        #pragma unroll
        for (int w = 0; w < 8; w++) s += red[w];
        atomicAdd(out, s * scale);
    }
}

// ---------------------------------------------------------------------------
// Launch
// ---------------------------------------------------------------------------
extern "C" void kernel_launch(void* const* d_in, const int* in_sizes, int n_in,
                              void* d_out, int out_size) {
    const float* emb  = (const float*)d_in[0];   // [B, D] fp32
    const float* text = (const float*)d_in[1];   // [B, B] fp32
    float* out = (float*)d_out;

    const int B = (int)(sqrt((double)in_sizes[1]) + 0.5);   // 8192
    const double count = (double)B * (double)(B - 1) / 2.0;
    const float scale = (float)(0.1 / count);

    cudaFuncSetAttribute(loss_kernel,
                         cudaFuncAttributeMaxDynamicSharedMemorySize, SMEM_TOTAL);

    zero_out_kernel<<<1, 1>>>(out);
    normalize_kernel<<<B / 8, 256>>>(emb, B);

    const int NT = B / 128;
    const int nblocks = NT * (NT + 1) / 2;   // 2080 upper-tri tiles
    loss_kernel<<<nblocks, 256, SMEM_TOTAL>>>(text, out, B, scale);
}

// round 6
// speedup vs baseline: 3.7852x; 1.0936x over previous
#include <cuda_runtime.h>
#include <cuda_bf16.h>
#include <cstdint>
#include <math.h>

// Normalized embeddings scratch (bf16): 8192 * 256 * 2B = 4 MB, L2-resident.
__device__ __nv_bfloat16 g_en[8192 * 256];

// ---------------------------------------------------------------------------
// Kernel 1: row-normalize embeddings (fp32 -> bf16). One warp per row, D=256.
// Also zeroes the (poisoned) output scalar from block 0.
// ---------------------------------------------------------------------------
__global__ void normalize_kernel(const float* __restrict__ emb, int B,
                                 float* __restrict__ out) {
    if (blockIdx.x == 0 && threadIdx.x == 0) out[0] = 0.0f;

    const int warpId = threadIdx.x >> 5;
    const int lane   = threadIdx.x & 31;
    const int row    = blockIdx.x * 8 + warpId;
    if (row >= B) return;

    const float4* p = reinterpret_cast<const float4*>(emb + (size_t)row * 256);
    float4 v0 = p[lane];
    float4 v1 = p[lane + 32];

    float ss = v0.x * v0.x + v0.y * v0.y + v0.z * v0.z + v0.w * v0.w
             + v1.x * v1.x + v1.y * v1.y + v1.z * v1.z + v1.w * v1.w;
    #pragma unroll
    for (int o = 16; o > 0; o >>= 1) ss += __shfl_xor_sync(0xffffffffu, ss, o);

    const float scale = 1.0f / fmaxf(sqrtf(ss), 1e-8f);

    __nv_bfloat162 a0 = __floats2bfloat162_rn(v0.x * scale, v0.y * scale);
    __nv_bfloat162 a1 = __floats2bfloat162_rn(v0.z * scale, v0.w * scale);
    __nv_bfloat162 b0 = __floats2bfloat162_rn(v1.x * scale, v1.y * scale);
    __nv_bfloat162 b1 = __floats2bfloat162_rn(v1.z * scale, v1.w * scale);

    uint2 ua, ub;
    ua.x = *reinterpret_cast<unsigned*>(&a0);
    ua.y = *reinterpret_cast<unsigned*>(&a1);
    ub.x = *reinterpret_cast<unsigned*>(&b0);
    ub.y = *reinterpret_cast<unsigned*>(&b1);

    uint2* orow = reinterpret_cast<uint2*>(g_en + (size_t)row * 256);
    orow[lane]      = ua;
    orow[lane + 32] = ub;
}

// ---------------------------------------------------------------------------
// Kernel 2: fused cos-GEMM tile + |text - cos| masked reduction.
// mma.sync.m16n8k16 (bf16 -> fp32), in-register epilogue, text via direct LDG.
//
// One CTA = one 128x128 upper-triangular tile, K = 256 processed as four
// K=64 chunks with double-buffered cp.async staging (stage ch+2 while
// computing ch). smem = 72 KB -> 2 CTAs/SM so staging of one CTA overlaps
// MMA of the other.
//
// Chunk strip: 128 rows x 64 bf16, padded to 144 B rows (144 mod 128 = 16 ->
// conflict-free ldmatrix). Buffer = A strip + B strip = 36864 B, x2 buffers.
// ---------------------------------------------------------------------------
#define LDM_OP     72                      // bf16 elems per padded chunk row
#define ROW_BYTES  144
#define STRIP_B    (128 * ROW_BYTES)       // 18432
#define BUF_B      (2 * STRIP_B)           // 36864 (A strip + B strip)
#define SMEM_TOTAL (2 * BUF_B)             // 73728

#define LDSM4(R0, R1, R2, R3, ADDR)                                          \
    asm volatile("ldmatrix.sync.aligned.m8n8.x4.shared.b16 {%0,%1,%2,%3}, [%4];" \
                 : "=r"(R0), "=r"(R1), "=r"(R2), "=r"(R3) : "r"(ADDR))

#define MMA16816(C, A, B0, B1)                                               \
    asm volatile("mma.sync.aligned.m16n8k16.row.col.f32.bf16.bf16.f32 "      \
                 "{%0,%1,%2,%3}, {%4,%5,%6,%7}, {%8,%9}, {%0,%1,%2,%3};"     \
                 : "+f"((C)[0]), "+f"((C)[1]), "+f"((C)[2]), "+f"((C)[3])    \
                 : "r"((A)[0]), "r"((A)[1]), "r"((A)[2]), "r"((A)[3]),       \
                   "r"(B0), "r"(B1))

// Stage one K=64 chunk (A rows from by-strip, B rows from bx-strip) into buf.
__device__ __forceinline__ void stage_chunk(uint32_t sbase, int buf, int ch,
                                            const char* Ag, const char* Bg,
                                            int tid) {
    const uint32_t aDst = sbase + (uint32_t)buf * BUF_B;
    const uint32_t bDst = aDst + STRIP_B;
    const size_t gchunk = (size_t)ch * 128;           // byte offset of chunk cols
    #pragma unroll
    for (int i = tid; i < 1024; i += 256) {           // 128 rows x 8 x 16B
        const int r = i >> 3;
        const int c = i & 7;
        const uint32_t soff = (uint32_t)r * ROW_BYTES + (uint32_t)c * 16;
        const size_t   goff = (size_t)r * 512 + gchunk + (size_t)c * 16;
        asm volatile("cp.async.cg.shared.global [%0], [%1], 16;"
                     :: "r"(aDst + soff), "l"(Ag + goff) : "memory");
        asm volatile("cp.async.cg.shared.global [%0], [%1], 16;"
                     :: "r"(bDst + soff), "l"(Bg + goff) : "memory");
    }
    asm volatile("cp.async.commit_group;" ::: "memory");
}

__global__ __launch_bounds__(256, 2)
void loss_kernel(const float* __restrict__ text, float* __restrict__ out,
                 int B, float scale) {
    extern __shared__ char smem[];
    uint32_t sbase;
    asm("{ .reg .u64 t; cvta.to.shared.u64 t, %1; cvt.u32.u64 %0, t; }"
        : "=r"(sbase) : "l"((const void*)smem));

    const int tid = threadIdx.x;

    // ---- linear block id -> upper-triangular (by, bx), by <= bx ----
    const int NT = B >> 7;
    int t = blockIdx.x;
    int by = 0;
    while (t >= NT - by) { t -= NT - by; ++by; }
    const int bx = by + t;

    const char* __restrict__ Ag =
        reinterpret_cast<const char*>(g_en + (size_t)by * 128 * 256);
    const char* __restrict__ Bg =
        reinterpret_cast<const char*>(g_en + (size_t)bx * 128 * 256);

    // ---- prologue: stage chunks 0,1 into buffers 0,1 ----
    stage_chunk(sbase, 0, 0, Ag, Bg, tid);
    stage_chunk(sbase, 1, 1, Ag, Bg, tid);

    // ---- warp / fragment geometry ----
    const int warpId = tid >> 5;
    const int lane   = tid & 31;
    const int wr = warpId & 3;    // 32-row strip
    const int wc = warpId >> 2;   // 64-col strip
    const int grp = lane >> 3;

    const uint32_t aOff =
        (uint32_t)(((wr * 32 + (lane & 15)) * LDM_OP + (lane >> 4) * 8) * 2);
    const uint32_t bOff = (uint32_t)STRIP_B +
        (uint32_t)(((wc * 64 + (grp >> 1) * 8 + (lane & 7)) * LDM_OP + (grp & 1) * 8) * 2);

    float c[2][8][4];
    #pragma unroll
    for (int mt = 0; mt < 2; mt++)
        #pragma unroll
        for (int nt = 0; nt < 8; nt++)
            #pragma unroll
            for (int e = 0; e < 4; e++) c[mt][nt][e] = 0.0f;

    // ---- mainloop over 4 K-chunks, double-buffered ----
    #pragma unroll
    for (int ch = 0; ch < 4; ch++) {
        if (ch < 3) {
            asm volatile("cp.async.wait_group 1;" ::: "memory");
        } else {
            asm volatile("cp.async.wait_group 0;" ::: "memory");
        }
        __syncthreads();

        const uint32_t bufBase = sbase + (uint32_t)(ch & 1) * BUF_B;
        #pragma unroll
        for (int kc = 0; kc < 4; kc++) {
            const uint32_t koff = (uint32_t)(kc * 32);   // 16 bf16 = 32 B
            uint32_t a[2][4];
            #pragma unroll
            for (int mt = 0; mt < 2; mt++)
                LDSM4(a[mt][0], a[mt][1], a[mt][2], a[mt][3],
                      bufBase + aOff + (uint32_t)(mt * 16 * ROW_BYTES) + koff);
            uint32_t b[4][4];
            #pragma unroll
            for (int p = 0; p < 4; p++)
                LDSM4(b[p][0], b[p][1], b[p][2], b[p][3],
                      bufBase + bOff + (uint32_t)(p * 16 * ROW_BYTES) + koff);
            #pragma unroll
            for (int mt = 0; mt < 2; mt++)
                #pragma unroll
                for (int nt = 0; nt < 8; nt++)
                    MMA16816(c[mt][nt], a[mt],
                             b[nt >> 1][(nt & 1) * 2], b[nt >> 1][(nt & 1) * 2 + 1]);
        }

        if (ch < 2) {
            __syncthreads();   // all warps done reading this buffer
            stage_chunk(sbase, ch & 1, ch + 2, Ag, Bg, tid);
        }
    }

    // ---- epilogue: |text - cos| with i<j mask, text via direct LDG ----
    const int qrow = lane >> 2;          // 0..7
    const int qcol = (lane & 3) * 2;     // 0,2,4,6
    const bool diag = (bx == by);

    float acc = 0.0f;
    #pragma unroll
    for (int mt = 0; mt < 2; mt++) {
        const int r0 = wr * 32 + mt * 16 + qrow;        // rows r0, r0+8
        const int gi0 = by * 128 + r0;
        const float* __restrict__ trow0 = text + (size_t)gi0 * B + bx * 128;
        const float* __restrict__ trow1 = trow0 + (size_t)8 * B;
        #pragma unroll
        for (int nt = 0; nt < 8; nt++) {
            const int cc = wc * 64 + nt * 8 + qcol;
            const float2 t0 = *reinterpret_cast<const float2*>(trow0 + cc);
            const float2 t1 = *reinterpret_cast<const float2*>(trow1 + cc);
            const float* cf = c[mt][nt];
            if (!diag) {
                acc += fabsf(t0.x - cf[0]) + fabsf(t0.y - cf[1])
                     + fabsf(t1.x - cf[2]) + fabsf(t1.y - cf[3]);
            } else {
                if (cc     > r0)     acc += fabsf(t0.x - cf[0]);
                if (cc + 1 > r0)     acc += fabsf(t0.y - cf[1]);
                if (cc     > r0 + 8) acc += fabsf(t1.x - cf[2]);
                if (cc + 1 > r0 + 8) acc += fabsf(t1.y - cf[3]);
            }
        }
    }

    // ---- reduction: warp shuffle -> smem -> one atomicAdd ----
    #pragma unroll
    for (int o = 16; o > 0; o >>= 1) acc += __shfl_xor_sync(0xffffffffu, acc, o);

    __shared__ float red[8];
    if ((tid & 31) == 0) red[tid >> 5] = acc;
    __syncthreads();
    if (tid == 0) {
        float s = 0.0f;
        #pragma unroll
        for (int w = 0; w < 8; w++) s += red[w];
        atomicAdd(out, s * scale);
    }
}

// ---------------------------------------------------------------------------
// Launch
// ---------------------------------------------------------------------------
extern "C" void kernel_launch(void* const* d_in, const int* in_sizes, int n_in,
                              void* d_out, int out_size) {
    const float* emb  = (const float*)d_in[0];   // [B, D] fp32
    const float* text = (const float*)d_in[1];   // [B, B] fp32
    float* out = (float*)d_out;

    const int B = (int)(sqrt((double)in_sizes[1]) + 0.5);   // 8192
    const double count = (double)B * (double)(B - 1) / 2.0;
    const float scale = (float)(0.1 / count);

    cudaFuncSetAttribute(loss_kernel,
                         cudaFuncAttributeMaxDynamicSharedMemorySize, SMEM_TOTAL);

    normalize_kernel<<<B / 8, 256>>>(emb, B, out);

    const int NT = B / 128;
    const int nblocks = NT * (NT + 1) / 2;   // 2080 upper-tri tiles
    loss_kernel<<<nblocks, 256, SMEM_TOTAL>>>(text, out, B, scale);
}

// round 7
// speedup vs baseline: 4.4295x; 1.1702x over previous
#include <cuda_runtime.h>
#include <cuda_bf16.h>
#include <cstdint>
#include <math.h>

// Normalized embeddings scratch (bf16): 8192 * 256 * 2B = 4 MB, L2-resident.
__device__ __nv_bfloat16 g_en[8192 * 256];

// ---------------------------------------------------------------------------
// Kernel 1: row-normalize embeddings (fp32 -> bf16). One warp per row, D=256.
// Also zeroes the (poisoned) output scalar from block 0.
// ---------------------------------------------------------------------------
__global__ void normalize_kernel(const float* __restrict__ emb, int B,
                                 float* __restrict__ out) {
    if (blockIdx.x == 0 && threadIdx.x == 0) out[0] = 0.0f;

    const int warpId = threadIdx.x >> 5;
    const int lane   = threadIdx.x & 31;
    const int row    = blockIdx.x * 8 + warpId;
    if (row >= B) return;

    const float4* p = reinterpret_cast<const float4*>(emb + (size_t)row * 256);
    float4 v0 = p[lane];
    float4 v1 = p[lane + 32];

    float ss = v0.x * v0.x + v0.y * v0.y + v0.z * v0.z + v0.w * v0.w
             + v1.x * v1.x + v1.y * v1.y + v1.z * v1.z + v1.w * v1.w;
    #pragma unroll
    for (int o = 16; o > 0; o >>= 1) ss += __shfl_xor_sync(0xffffffffu, ss, o);

    const float scale = 1.0f / fmaxf(sqrtf(ss), 1e-8f);

    __nv_bfloat162 a0 = __floats2bfloat162_rn(v0.x * scale, v0.y * scale);
    __nv_bfloat162 a1 = __floats2bfloat162_rn(v0.z * scale, v0.w * scale);
    __nv_bfloat162 b0 = __floats2bfloat162_rn(v1.x * scale, v1.y * scale);
    __nv_bfloat162 b1 = __floats2bfloat162_rn(v1.z * scale, v1.w * scale);

    uint2 ua, ub;
    ua.x = *reinterpret_cast<unsigned*>(&a0);
    ua.y = *reinterpret_cast<unsigned*>(&a1);
    ub.x = *reinterpret_cast<unsigned*>(&b0);
    ub.y = *reinterpret_cast<unsigned*>(&b1);

    uint2* orow = reinterpret_cast<uint2*>(g_en + (size_t)row * 256);
    orow[lane]      = ua;
    orow[lane + 32] = ub;
}

// ---------------------------------------------------------------------------
// Kernel 2: fused cos-GEMM tile + |text - cos| masked reduction.
// mma.sync.m16n8k16 (bf16 -> fp32), in-register mainloop, all-smem epilogue.
//
// One CTA = one 128x128 upper-triangular tile, K = 256 as four K=64 chunks,
// double-buffered cp.async. text_sim tile fully prefetched via cp.async:
//   group2 = text rows 0-63  -> dedicated TEXT0 region (committed at start,
//            streams during the whole mainloop)
//   group5 = text rows 64-127 -> buf0 (reused after its last operand read,
//            streams during chunk-3 compute)
// cp.async groups complete in commit order, so the ladder is:
//   ch0: wait 2 | ch1: wait 2 | ch2: wait 1 | ch3: wait 1 | epi: wait 0.
// smem = 2*36864 (operand bufs) + 33792 (TEXT0) = 105 KB -> 2 CTAs/SM.
// Text rows padded to 132 floats (528 B): conflict-free epilogue reads.
// ---------------------------------------------------------------------------
#define LDM_OP     72                      // bf16 elems per padded chunk row
#define ROW_BYTES  144
#define STRIP_B    (128 * ROW_BYTES)       // 18432
#define BUF_B      (2 * STRIP_B)           // 36864 (A strip + B strip)
#define LDM_T      132                     // fp32 elems per padded text row
#define TROW_B     528
#define TEXT0_OFF  (2 * BUF_B)             // 73728
#define TEXT_HALF_B (64 * TROW_B)          // 33792
#define SMEM_TOTAL (TEXT0_OFF + TEXT_HALF_B)   // 107520

#define LDSM4(R0, R1, R2, R3, ADDR)                                          \
    asm volatile("ldmatrix.sync.aligned.m8n8.x4.shared.b16 {%0,%1,%2,%3}, [%4];" \
                 : "=r"(R0), "=r"(R1), "=r"(R2), "=r"(R3) : "r"(ADDR))

#define MMA16816(C, A, B0, B1)                                               \
    asm volatile("mma.sync.aligned.m16n8k16.row.col.f32.bf16.bf16.f32 "      \
                 "{%0,%1,%2,%3}, {%4,%5,%6,%7}, {%8,%9}, {%0,%1,%2,%3};"     \
                 : "+f"((C)[0]), "+f"((C)[1]), "+f"((C)[2]), "+f"((C)[3])    \
                 : "r"((A)[0]), "r"((A)[1]), "r"((A)[2]), "r"((A)[3]),       \
                   "r"(B0), "r"(B1))

// Stage one K=64 operand chunk (A + B strips) into buffer `buf`, commit.
__device__ __forceinline__ void stage_chunk(uint32_t sbase, int buf, int ch,
                                            const char* Ag, const char* Bg,
                                            int tid) {
    const uint32_t aDst = sbase + (uint32_t)buf * BUF_B;
    const uint32_t bDst = aDst + STRIP_B;
    const size_t gchunk = (size_t)ch * 128;
    #pragma unroll
    for (int i = tid; i < 1024; i += 256) {           // 128 rows x 8 x 16B
        const int r = i >> 3;
        const int c = i & 7;
        const uint32_t soff = (uint32_t)r * ROW_BYTES + (uint32_t)c * 16;
        const size_t   goff = (size_t)r * 512 + gchunk + (size_t)c * 16;
        asm volatile("cp.async.cg.shared.global [%0], [%1], 16;"
                     :: "r"(aDst + soff), "l"(Ag + goff) : "memory");
        asm volatile("cp.async.cg.shared.global [%0], [%1], 16;"
                     :: "r"(bDst + soff), "l"(Bg + goff) : "memory");
    }
    asm volatile("cp.async.commit_group;" ::: "memory");
}

// Stage 64 text rows (128 floats each) into smem at `dst` (528 B rows), commit.
__device__ __forceinline__ void stage_text_half(uint32_t dst, const char* tg,
                                                int B, int tid) {
    #pragma unroll
    for (int i = tid; i < 2048; i += 256) {           // 64 rows x 32 x 16B
        const int r = i >> 5;
        const int c = i & 31;
        asm volatile("cp.async.cg.shared.global [%0], [%1], 16;"
                     :: "r"(dst + (uint32_t)r * TROW_B + (uint32_t)c * 16),
                        "l"(tg + (size_t)r * B * 4 + (size_t)c * 16)
                     : "memory");
    }
    asm volatile("cp.async.commit_group;" ::: "memory");
}

__global__ __launch_bounds__(256, 2)
void loss_kernel(const float* __restrict__ text, float* __restrict__ out,
                 int B, float scale) {
    extern __shared__ char smem[];
    uint32_t sbase;
    asm("{ .reg .u64 t; cvta.to.shared.u64 t, %1; cvt.u32.u64 %0, t; }"
        : "=r"(sbase) : "l"((const void*)smem));

    const int tid = threadIdx.x;

    // ---- linear block id -> upper-triangular (by, bx), by <= bx ----
    const int NT = B >> 7;
    int t = blockIdx.x;
    int by = 0;
    while (t >= NT - by) { t -= NT - by; ++by; }
    const int bx = by + t;

    const char* __restrict__ Ag =
        reinterpret_cast<const char*>(g_en + (size_t)by * 128 * 256);
    const char* __restrict__ Bg =
        reinterpret_cast<const char*>(g_en + (size_t)bx * 128 * 256);
    const char* __restrict__ tg = reinterpret_cast<const char*>(
        text + (size_t)(by * 128) * B + (size_t)bx * 128);

    // ---- prologue: g0 = ch0, g1 = ch1, g2 = text rows 0-63 ----
    stage_chunk(sbase, 0, 0, Ag, Bg, tid);
    stage_chunk(sbase, 1, 1, Ag, Bg, tid);
    stage_text_half(sbase + TEXT0_OFF, tg, B, tid);

    // ---- warp / fragment geometry ----
    const int warpId = tid >> 5;
    const int lane   = tid & 31;
    const int wr = warpId & 3;    // 32-row strip
    const int wc = warpId >> 2;   // 64-col strip
    const int grp = lane >> 3;

    const uint32_t aOff =
        (uint32_t)(((wr * 32 + (lane & 15)) * LDM_OP + (lane >> 4) * 8) * 2);
    const uint32_t bOff = (uint32_t)STRIP_B +
        (uint32_t)(((wc * 64 + (grp >> 1) * 8 + (lane & 7)) * LDM_OP + (grp & 1) * 8) * 2);

    float c[2][8][4];
    #pragma unroll
    for (int mt = 0; mt < 2; mt++)
        #pragma unroll
        for (int nt = 0; nt < 8; nt++)
            #pragma unroll
            for (int e = 0; e < 4; e++) c[mt][nt][e] = 0.0f;

    // ---- mainloop over 4 K-chunks ----
    #pragma unroll
    for (int ch = 0; ch < 4; ch++) {
        if (ch < 2) {
            asm volatile("cp.async.wait_group 2;" ::: "memory");
        } else {
            asm volatile("cp.async.wait_group 1;" ::: "memory");
        }
        __syncthreads();

        const uint32_t bufBase = sbase + (uint32_t)(ch & 1) * BUF_B;
        #pragma unroll
        for (int kc = 0; kc < 4; kc++) {
            const uint32_t koff = (uint32_t)(kc * 32);   // 16 bf16 = 32 B
            uint32_t a[2][4];
            #pragma unroll
            for (int mt = 0; mt < 2; mt++)
                LDSM4(a[mt][0], a[mt][1], a[mt][2], a[mt][3],
                      bufBase + aOff + (uint32_t)(mt * 16 * ROW_BYTES) + koff);
            uint32_t b[4][4];
            #pragma unroll
            for (int p = 0; p < 4; p++)
                LDSM4(b[p][0], b[p][1], b[p][2], b[p][3],
                      bufBase + bOff + (uint32_t)(p * 16 * ROW_BYTES) + koff);
            #pragma unroll
            for (int mt = 0; mt < 2; mt++)
                #pragma unroll
                for (int nt = 0; nt < 8; nt++)
                    MMA16816(c[mt][nt], a[mt],
                             b[nt >> 1][(nt & 1) * 2], b[nt >> 1][(nt & 1) * 2 + 1]);
        }

        if (ch < 2) {
            __syncthreads();   // all warps done reading this buffer
            stage_chunk(sbase, ch & 1, ch + 2, Ag, Bg, tid);        // g3, g4
        } else if (ch == 2) {
            __syncthreads();   // buf0's last operand read is done
            stage_text_half(sbase, tg + (size_t)64 * B * 4, B, tid); // g5 -> buf0
        }
    }

    // ---- epilogue: all-smem |text - cos| with i<j mask ----
    asm volatile("cp.async.wait_group 0;" ::: "memory");
    __syncthreads();

    const int qrow = lane >> 2;          // 0..7
    const int qcol = (lane & 3) * 2;     // 0,2,4,6
    const bool diag = (bx == by);
    // rows 0-63 live at TEXT0_OFF, rows 64-127 at offset 0 (buf0)
    const float* __restrict__ Ts = reinterpret_cast<const float*>(
        smem + (wr < 2 ? TEXT0_OFF : 0));

    float acc = 0.0f;
    #pragma unroll
    for (int mt = 0; mt < 2; mt++) {
        const int r0 = wr * 32 + mt * 16 + qrow;        // tile rows r0, r0+8
        const int lr = r0 & 63;                          // row within half
        #pragma unroll
        for (int nt = 0; nt < 8; nt++) {
            const int cc = wc * 64 + nt * 8 + qcol;
            const float2 t0 = *reinterpret_cast<const float2*>(Ts + lr * LDM_T + cc);
            const float2 t1 = *reinterpret_cast<const float2*>(Ts + (lr + 8) * LDM_T + cc);
            const float* cf = c[mt][nt];
            if (!diag) {
                acc += fabsf(t0.x - cf[0]) + fabsf(t0.y - cf[1])
                     + fabsf(t1.x - cf[2]) + fabsf(t1.y - cf[3]);
            } else {
                if (cc     > r0)     acc += fabsf(t0.x - cf[0]);
                if (cc + 1 > r0)     acc += fabsf(t0.y - cf[1]);
                if (cc     > r0 + 8) acc += fabsf(t1.x - cf[2]);
                if (cc + 1 > r0 + 8) acc += fabsf(t1.y - cf[3]);
            }
        }
    }

    // ---- reduction: warp shuffle -> smem -> one atomicAdd ----
    #pragma unroll
    for (int o = 16; o > 0; o >>= 1) acc += __shfl_xor_sync(0xffffffffu, acc, o);

    __shared__ float red[8];
    if ((tid & 31) == 0) red[tid >> 5] = acc;
    __syncthreads();
    if (tid == 0) {
        float s = 0.0f;
        #pragma unroll
        for (int w = 0; w < 8; w++) s += red[w];
        atomicAdd(out, s * scale);
    }
}

// ---------------------------------------------------------------------------
// Launch
// ---------------------------------------------------------------------------
extern "C" void kernel_launch(void* const* d_in, const int* in_sizes, int n_in,
                              void* d_out, int out_size) {
    const float* emb  = (const float*)d_in[0];   // [B, D] fp32
    const float* text = (const float*)d_in[1];   // [B, B] fp32
    float* out = (float*)d_out;

    const int B = (int)(sqrt((double)in_sizes[1]) + 0.5);   // 8192
    const double count = (double)B * (double)(B - 1) / 2.0;
    const float scale = (float)(0.1 / count);

    cudaFuncSetAttribute(loss_kernel,
                         cudaFuncAttributeMaxDynamicSharedMemorySize, SMEM_TOTAL);

    normalize_kernel<<<B / 8, 256>>>(emb, B, out);

    const int NT = B / 128;
    const int nblocks = NT * (NT + 1) / 2;   // 2080 upper-tri tiles
    loss_kernel<<<nblocks, 256, SMEM_TOTAL>>>(text, out, B, scale);
}